// round 6
// baseline (speedup 1.0000x reference)
#include <cuda_runtime.h>
#include <cstdint>

#define TT     224
#define HH     128
#define BB     64
#define SS     20
#define NN     1280      // BB*SS
#define G4     4         // sequences per LSTM CTA
#define NG     320       // NN/G4
#define NINTER 64
#define KSPLIT 4
#define TM     16        // seq tile in feats GEMM
#define TCHUNK 56        // 224/KSPLIT timesteps per k-split

typedef unsigned long long u64;

// ---------------- scratch (static device globals; no runtime allocation) ---------
__device__ __align__(16) float g_hs[(size_t)NN * TT * HH];   // [n][t][h], ~147MB
__device__ int   g_len[NN];
__device__ int   g_order[NN];
__device__ int   g_hist[256];
__device__ int   g_off[256];
__device__ __align__(16) float g_Wt[512 * 128];              // transposed W_hh
__device__ __align__(16) float g_psum[(size_t)KSPLIT * NN * NINTER];

// ---------------- helpers ----------------
__device__ __forceinline__ u64 ffma2(u64 a, u64 b, u64 c) {
    u64 d;
    asm("fma.rn.f32x2 %0, %1, %2, %3;" : "=l"(d) : "l"(a), "l"(b), "l"(c));
    return d;
}
__device__ __forceinline__ float f2lo(u64 v) { return __uint_as_float((unsigned)(v & 0xffffffffull)); }
__device__ __forceinline__ float f2hi(u64 v) { return __uint_as_float((unsigned)(v >> 32)); }
__device__ __forceinline__ float sigf(float v) { return 1.0f / (1.0f + __expf(-v)); }

// ---------------- kernel 0: zero histogram (state must reset every launch) ------
__global__ void k_zero_hist() {
    if (threadIdx.x < 256) g_hist[threadIdx.x] = 0;
}

// ---------------- kernel 1: ragged lengths + histogram ---------------------------
// reference: maxes = argmax(x==0, axis=time); len = (maxes==0) ? T : maxes+1
__global__ void k_lens(const float* __restrict__ x) {
    int n = blockIdx.x;
    const float* xs = x + (size_t)n * TT;
    int first = 1 << 30;
    for (int t = threadIdx.x; t < TT; t += 32)
        if (xs[t] == 0.0f) first = min(first, t);
    #pragma unroll
    for (int o = 16; o; o >>= 1)
        first = min(first, __shfl_xor_sync(0xffffffffu, first, o));
    if (threadIdx.x == 0) {
        int len = (first == 0 || first >= TT) ? TT : (first + 1);
        g_len[n] = len;
        atomicAdd(&g_hist[len], 1);
    }
}

// ---------------- kernel 2: prefix sum over hist ---------------------------------
__global__ void k_prefix() {
    if (threadIdx.x == 0) {
        int acc = 0;
        for (int i = 0; i < 256; i++) { g_off[i] = acc; acc += g_hist[i]; }
    }
}

// ---------------- kernel 3: counting-sort scatter (ascending by len) -------------
__global__ void k_scatter() {
    int n = blockIdx.x * blockDim.x + threadIdx.x;
    if (n < NN) {
        int pos = atomicAdd(&g_off[g_len[n]], 1);
        g_order[pos] = n;
    }
}

// ---------------- kernel 4: transpose W_hh into warp-contiguous layout ----------
// dst float4 index i = ((w*32 + kq)*4 + gate)*32 + lane ;  row = gate*128 + w*32 + lane
__global__ void k_wt(const float* __restrict__ Whh) {
    int i = blockIdx.x * blockDim.x + threadIdx.x;   // 0..16383
    int l  = i & 31;
    int gg = (i >> 5) & 3;
    int kq = (i >> 7) & 31;
    int w  = i >> 12;
    int r  = gg * 128 + w * 32 + l;
    float4 v = ((const float4*)Whh)[r * 32 + kq];
    ((float4*)g_Wt)[i] = v;
}

// ---------------- kernel 5: batched LSTM (M=4 sequences per CTA) -----------------
__global__ void __launch_bounds__(128) k_lstm(
    const float* __restrict__ x, const float* __restrict__ Wih,
    const float* __restrict__ bih, const float* __restrict__ bhh)
{
    __shared__ float sx[G4][TT];
    __shared__ __align__(16) u64 sh[2][G4][HH / 2];  // h as f32x2 pairs, double-buffered
    __shared__ int sn[G4], sl[G4];

    int tid = threadIdx.x;
    int g = (NG - 1) - blockIdx.x;   // longest groups scheduled first
    if (tid < G4) {
        int n = g_order[g * G4 + tid];
        sn[tid] = n;
        sl[tid] = g_len[n];
    }
    __syncthreads();
    int n0 = sn[0], n1 = sn[1], n2 = sn[2], n3 = sn[3];
    int l0 = sl[0], l1 = sl[1], l2 = sl[2], l3 = sl[3];
    int maxlen = max(max(l0, l1), max(l2, l3));

    #pragma unroll
    for (int m = 0; m < G4; m++)
        for (int t = tid; t < TT; t += 128) sx[m][t] = x[(size_t)sn[m] * TT + t];
    for (int i = tid; i < G4 * (HH / 2); i += 128) ((u64*)sh[0])[i] = 0ull;

    // per-thread gate constants (thread tid = hidden unit tid; gates i,f,g,o)
    float wi[4], bs[4];
    #pragma unroll
    for (int gg = 0; gg < 4; gg++) {
        int r = gg * HH + tid;
        wi[gg] = Wih[r];
        bs[gg] = bih[r] + bhh[r];
    }
    int w = tid >> 5, l = tid & 31;
    const ulonglong2* wt = ((const ulonglong2*)g_Wt) + (size_t)w * (32 * 4 * 32) + l;

    float c0 = 0.f, c1 = 0.f, c2 = 0.f, c3 = 0.f;
    float* hs0 = g_hs + (size_t)n0 * TT * HH + tid;
    float* hs1 = g_hs + (size_t)n1 * TT * HH + tid;
    float* hs2 = g_hs + (size_t)n2 * TT * HH + tid;
    float* hs3 = g_hs + (size_t)n3 * TT * HH + tid;
    __syncthreads();

    for (int t = 0; t < maxlen; t++) {
        int cur = t & 1, nxt = cur ^ 1;
        const ulonglong2* hp0 = (const ulonglong2*)sh[cur][0];
        const ulonglong2* hp1 = (const ulonglong2*)sh[cur][1];
        const ulonglong2* hp2 = (const ulonglong2*)sh[cur][2];
        const ulonglong2* hp3 = (const ulonglong2*)sh[cur][3];

        u64 a00 = 0, a10 = 0, a20 = 0, a30 = 0;
        u64 a01 = 0, a11 = 0, a21 = 0, a31 = 0;
        u64 a02 = 0, a12 = 0, a22 = 0, a32 = 0;
        u64 a03 = 0, a13 = 0, a23 = 0, a33 = 0;

        #pragma unroll 4
        for (int kq = 0; kq < 32; kq++) {
            const ulonglong2* wk = wt + kq * 128;
            ulonglong2 W0 = wk[0];
            ulonglong2 W1 = wk[32];
            ulonglong2 W2 = wk[64];
            ulonglong2 W3 = wk[96];
            ulonglong2 h0 = hp0[kq], h1 = hp1[kq], h2 = hp2[kq], h3 = hp3[kq];

            a00 = ffma2(W0.x, h0.x, a00); a00 = ffma2(W0.y, h0.y, a00);
            a10 = ffma2(W1.x, h0.x, a10); a10 = ffma2(W1.y, h0.y, a10);
            a20 = ffma2(W2.x, h0.x, a20); a20 = ffma2(W2.y, h0.y, a20);
            a30 = ffma2(W3.x, h0.x, a30); a30 = ffma2(W3.y, h0.y, a30);

            a01 = ffma2(W0.x, h1.x, a01); a01 = ffma2(W0.y, h1.y, a01);
            a11 = ffma2(W1.x, h1.x, a11); a11 = ffma2(W1.y, h1.y, a11);
            a21 = ffma2(W2.x, h1.x, a21); a21 = ffma2(W2.y, h1.y, a21);
            a31 = ffma2(W3.x, h1.x, a31); a31 = ffma2(W3.y, h1.y, a31);

            a02 = ffma2(W0.x, h2.x, a02); a02 = ffma2(W0.y, h2.y, a02);
            a12 = ffma2(W1.x, h2.x, a12); a12 = ffma2(W1.y, h2.y, a12);
            a22 = ffma2(W2.x, h2.x, a22); a22 = ffma2(W2.y, h2.y, a22);
            a32 = ffma2(W3.x, h2.x, a32); a32 = ffma2(W3.y, h2.y, a32);

            a03 = ffma2(W0.x, h3.x, a03); a03 = ffma2(W0.y, h3.y, a03);
            a13 = ffma2(W1.x, h3.x, a13); a13 = ffma2(W1.y, h3.y, a13);
            a23 = ffma2(W2.x, h3.x, a23); a23 = ffma2(W2.y, h3.y, a23);
            a33 = ffma2(W3.x, h3.x, a33); a33 = ffma2(W3.y, h3.y, a33);
        }

        float xt0 = sx[0][t], xt1 = sx[1][t], xt2 = sx[2][t], xt3 = sx[3][t];

        // m = 0
        {
            float pi = f2lo(a00) + f2hi(a00) + xt0 * wi[0] + bs[0];
            float pf = f2lo(a10) + f2hi(a10) + xt0 * wi[1] + bs[1];
            float pg = f2lo(a20) + f2hi(a20) + xt0 * wi[2] + bs[2];
            float po = f2lo(a30) + f2hi(a30) + xt0 * wi[3] + bs[3];
            c0 = sigf(pf) * c0 + sigf(pi) * tanhf(pg);
            float hv = sigf(po) * tanhf(c0);
            ((float*)sh[nxt][0])[tid] = hv;
            if (t < l0) hs0[(size_t)t * HH] = hv;
        }
        // m = 1
        {
            float pi = f2lo(a01) + f2hi(a01) + xt1 * wi[0] + bs[0];
            float pf = f2lo(a11) + f2hi(a11) + xt1 * wi[1] + bs[1];
            float pg = f2lo(a21) + f2hi(a21) + xt1 * wi[2] + bs[2];
            float po = f2lo(a31) + f2hi(a31) + xt1 * wi[3] + bs[3];
            c1 = sigf(pf) * c1 + sigf(pi) * tanhf(pg);
            float hv = sigf(po) * tanhf(c1);
            ((float*)sh[nxt][1])[tid] = hv;
            if (t < l1) hs1[(size_t)t * HH] = hv;
        }
        // m = 2
        {
            float pi = f2lo(a02) + f2hi(a02) + xt2 * wi[0] + bs[0];
            float pf = f2lo(a12) + f2hi(a12) + xt2 * wi[1] + bs[1];
            float pg = f2lo(a22) + f2hi(a22) + xt2 * wi[2] + bs[2];
            float po = f2lo(a32) + f2hi(a32) + xt2 * wi[3] + bs[3];
            c2 = sigf(pf) * c2 + sigf(pi) * tanhf(pg);
            float hv = sigf(po) * tanhf(c2);
            ((float*)sh[nxt][2])[tid] = hv;
            if (t < l2) hs2[(size_t)t * HH] = hv;
        }
        // m = 3
        {
            float pi = f2lo(a03) + f2hi(a03) + xt3 * wi[0] + bs[0];
            float pf = f2lo(a13) + f2hi(a13) + xt3 * wi[1] + bs[1];
            float pg = f2lo(a23) + f2hi(a23) + xt3 * wi[2] + bs[2];
            float po = f2lo(a33) + f2hi(a33) + xt3 * wi[3] + bs[3];
            c3 = sigf(pf) * c3 + sigf(pi) * tanhf(pg);
            float hv = sigf(po) * tanhf(c3);
            ((float*)sh[nxt][3])[tid] = hv;
            if (t < l3) hs3[(size_t)t * HH] = hv;
        }
        __syncthreads();
    }

    // zero the masked tails so the feats GEMM can ignore lengths
    #pragma unroll
    for (int m = 0; m < G4; m++) {
        int n = sn[m];
        for (int t = sl[m]; t < TT; t++)
            g_hs[((size_t)n * TT + t) * HH + tid] = 0.0f;
    }
}

// ---------------- kernel 6: feats GEMM (split-K, tiled, f32x2) -------------------
// psum[kz][n][j] = sum_{t in chunk} sum_h hs[n][t][h] * W1[j][t*128+h]
__global__ void __launch_bounds__(256) k_feats(const float* __restrict__ W1) {
    __shared__ __align__(16) float sh_hs[TM][HH];       // 8 KB
    __shared__ __align__(16) float sh_w[NINTER][HH];    // 32 KB

    int tile = blockIdx.x;        // 0..79
    int kz = blockIdx.y;          // 0..3
    int tid = threadIdx.x;
    int s0 = (tid & 7) * 2;       // 2 sequence rows
    int j0 = (tid >> 3) * 2;      // 2 inter cols
    u64 a00 = 0, a01 = 0, a10 = 0, a11 = 0;

    int t0 = kz * TCHUNK;
    for (int tt = 0; tt < TCHUNK; tt++) {
        int t = t0 + tt;
        __syncthreads();
        for (int i = tid; i < TM * HH / 4; i += 256) {
            int s = i >> 5, kq = i & 31;
            ((float4*)sh_hs[s])[kq] =
                ((const float4*)(g_hs + ((size_t)(tile * TM + s) * TT + t) * HH))[kq];
        }
        for (int i = tid; i < NINTER * HH / 4; i += 256) {
            int j = i >> 5, kq = i & 31;
            ((float4*)sh_w[j])[kq] =
                ((const float4*)(W1 + (size_t)j * (TT * HH) + (size_t)t * HH))[kq];
        }
        __syncthreads();
        #pragma unroll 8
        for (int kq = 0; kq < HH / 4; kq++) {
            ulonglong2 hA = ((const ulonglong2*)sh_hs[s0])[kq];
            ulonglong2 hB = ((const ulonglong2*)sh_hs[s0 + 1])[kq];
            ulonglong2 wA = ((const ulonglong2*)sh_w[j0])[kq];
            ulonglong2 wB = ((const ulonglong2*)sh_w[j0 + 1])[kq];
            a00 = ffma2(hA.x, wA.x, a00); a00 = ffma2(hA.y, wA.y, a00);
            a01 = ffma2(hA.x, wB.x, a01); a01 = ffma2(hA.y, wB.y, a01);
            a10 = ffma2(hB.x, wA.x, a10); a10 = ffma2(hB.y, wA.y, a10);
            a11 = ffma2(hB.x, wB.x, a11); a11 = ffma2(hB.y, wB.y, a11);
        }
    }
    size_t base = ((size_t)kz * NN + (tile * TM + s0)) * NINTER;
    g_psum[base + j0]              = f2lo(a00) + f2hi(a00);
    g_psum[base + j0 + 1]          = f2lo(a01) + f2hi(a01);
    g_psum[base + NINTER + j0]     = f2lo(a10) + f2hi(a10);
    g_psum[base + NINTER + j0 + 1] = f2lo(a11) + f2hi(a11);
}

// ---------------- kernel 7: reduce split-K + bias + final linear -----------------
__global__ void __launch_bounds__(256) k_final(
    const float* __restrict__ b1, const float* __restrict__ W2,
    const float* __restrict__ b2, float* __restrict__ out)
{
    __shared__ float sf[SS * NINTER];   // 1280 feats for this batch
    __shared__ float r0[256], r1[256];
    int b = blockIdx.x, tid = threadIdx.x;

    for (int i = tid; i < SS * NINTER; i += 256) {
        int s = i / NINTER, j = i % NINTER;
        size_t nq = (size_t)b * SS + s;
        float v = b1[j];
        #pragma unroll
        for (int kz = 0; kz < KSPLIT; kz++)
            v += g_psum[((size_t)kz * NN + nq) * NINTER + j];
        sf[i] = v;
    }
    __syncthreads();
    float p0 = 0.f, p1 = 0.f;
    for (int i = tid; i < SS * NINTER; i += 256) {
        float f = sf[i];
        p0 += f * W2[i];
        p1 += f * W2[SS * NINTER + i];
    }
    r0[tid] = p0; r1[tid] = p1;
    __syncthreads();
    for (int off = 128; off; off >>= 1) {
        if (tid < off) { r0[tid] += r0[tid + off]; r1[tid] += r1[tid + off]; }
        __syncthreads();
    }
    if (tid == 0) {
        out[b * 2 + 0] = r0[0] + b2[0];
        out[b * 2 + 1] = r1[0] + b2[1];
    }
}

// ---------------- launch ----------------------------------------------------------
extern "C" void kernel_launch(void* const* d_in, const int* in_sizes, int n_in,
                              void* d_out, int out_size)
{
    const float* x   = (const float*)d_in[0];
    // d_in[1] = metadata (unused by the reference computation)
    const float* Wih = (const float*)d_in[2];
    const float* Whh = (const float*)d_in[3];
    const float* bih = (const float*)d_in[4];
    const float* bhh = (const float*)d_in[5];
    const float* W1  = (const float*)d_in[6];
    const float* b1  = (const float*)d_in[7];
    const float* W2  = (const float*)d_in[8];
    const float* b2  = (const float*)d_in[9];
    float* out = (float*)d_out;

    k_zero_hist<<<1, 256>>>();
    k_lens<<<NN, 32>>>(x);
    k_prefix<<<1, 32>>>();
    k_scatter<<<5, 256>>>();
    k_wt<<<64, 256>>>(Whh);
    k_lstm<<<NG, 128>>>(x, Wih, bih, bhh);
    k_feats<<<dim3(80, KSPLIT), 256>>>(W1);
    k_final<<<BB, 256>>>(b1, W2, b2, out);
}

// round 7
// speedup vs baseline: 3.1350x; 3.1350x over previous
#include <cuda_runtime.h>
#include <cstdint>

#define TT     224
#define HH     128
#define BB     64
#define SS     20
#define NN     1280      // BB*SS
#define G4     4         // sequences per LSTM CTA
#define NG     320       // NN/G4
#define NINTER 64
#define KSPLIT 8
#define TM     32        // seq tile in feats GEMM
#define TCHUNK 28        // 224/KSPLIT timesteps per k-split

typedef unsigned long long u64;

// ---------------- scratch (static device globals; no runtime allocation) ---------
__device__ __align__(16) float g_hs[(size_t)NN * TT * HH];   // [n][t][h]
__device__ int   g_len[NN];
__device__ int   g_order[NN];
__device__ int   g_hist[256];
__device__ int   g_off[256];
__device__ __align__(16) float g_Wk[512 * 128];              // [p2][r] float4: W[r][4p2..4p2+3]
__device__ __align__(16) float g_psum[(size_t)KSPLIT * NN * NINTER];

// ---------------- helpers ----------------
__device__ __forceinline__ u64 ffma2(u64 a, u64 b, u64 c) {
    u64 d;
    asm("fma.rn.f32x2 %0, %1, %2, %3;" : "=l"(d) : "l"(a), "l"(b), "l"(c));
    return d;
}
__device__ __forceinline__ float f2lo(u64 v) { return __uint_as_float((unsigned)(v & 0xffffffffull)); }
__device__ __forceinline__ float f2hi(u64 v) { return __uint_as_float((unsigned)(v >> 32)); }
__device__ __forceinline__ float sigf(float v) { return 1.0f / (1.0f + __expf(-v)); }
__device__ __forceinline__ float tanh_(float v) {
    float e = __expf(-2.0f * v);
    return (1.0f - e) / (1.0f + e);
}

// ---------------- kernel 0: zero histogram ---------------------------------------
__global__ void k_zero_hist() {
    if (threadIdx.x < 256) g_hist[threadIdx.x] = 0;
}

// ---------------- kernel 1: ragged lengths + histogram ---------------------------
__global__ void k_lens(const float* __restrict__ x) {
    int n = blockIdx.x;
    const float* xs = x + (size_t)n * TT;
    int first = 1 << 30;
    for (int t = threadIdx.x; t < TT; t += 32)
        if (xs[t] == 0.0f) first = min(first, t);
    #pragma unroll
    for (int o = 16; o; o >>= 1)
        first = min(first, __shfl_xor_sync(0xffffffffu, first, o));
    if (threadIdx.x == 0) {
        int len = (first == 0 || first >= TT) ? TT : (first + 1);
        g_len[n] = len;
        atomicAdd(&g_hist[len], 1);
    }
}

// ---------------- kernel 2: prefix sum over hist ---------------------------------
__global__ void k_prefix() {
    if (threadIdx.x == 0) {
        int acc = 0;
        for (int i = 0; i < 256; i++) { g_off[i] = acc; acc += g_hist[i]; }
    }
}

// ---------------- kernel 3: counting-sort scatter (ascending by len) -------------
__global__ void k_scatter() {
    int n = blockIdx.x * blockDim.x + threadIdx.x;
    if (n < NN) {
        int pos = atomicAdd(&g_off[g_len[n]], 1);
        g_order[pos] = n;
    }
}

// ---------------- kernel 4: repack W_hh: g_Wk[p2*512 + r] = W[r][4p2..4p2+3] -----
__global__ void k_wt(const float* __restrict__ Whh) {
    int j = blockIdx.x * blockDim.x + threadIdx.x;   // 0..16383
    int r  = j & 511;
    int p2 = j >> 9;
    float4 v = ((const float4*)Whh)[r * 32 + p2];
    ((float4*)g_Wk)[p2 * 512 + r] = v;
}

// ---------------- kernel 5: LSTM, weights resident in smem+registers -------------
// 256 threads; thread owns gate-rows r0=tid, r1=tid+256 for 4 sequences.
// dynamic smem layout:
//   [0, 131072)        sWs  : ulonglong2[16*512]  weight k-quads p2=0..15
//   [131072, 135168)   shf  : float[2][4][128]    double-buffered h
//   [135168, 143360)   spre : float[4][4][128]    gate pre-activations
//   [143360, 146944)   sx   : float[4][224]
#define LSTM_SMEM 146944
__global__ void __launch_bounds__(256, 1) k_lstm(
    const float* __restrict__ x, const float* __restrict__ Wih,
    const float* __restrict__ bih, const float* __restrict__ bhh)
{
    extern __shared__ __align__(16) char dyn[];
    ulonglong2* sWs = (ulonglong2*)dyn;
    float* shf  = (float*)(dyn + 131072);
    float* spre = (float*)(dyn + 135168);
    float* sx   = (float*)(dyn + 143360);
    __shared__ int sn[G4], sl[G4];

    int tid = threadIdx.x;
    int g = (NG - 1) - blockIdx.x;   // longest groups first
    if (tid < G4) {
        int n = g_order[g * G4 + tid];
        sn[tid] = n;
        sl[tid] = g_len[n];
    }

    // stage smem weight half (p2 = 0..15)
    const float4* Wk4 = (const float4*)g_Wk;
    float4* sW4 = (float4*)sWs;
    for (int i = tid; i < 16 * 512; i += 256) sW4[i] = Wk4[i];
    // zero both h buffers
    for (int i = tid; i < 1024; i += 256) shf[i] = 0.0f;

    // register weight half (p2 = 16..31)
    ulonglong2 wr0[16], wr1[16];
    const ulonglong2* Wk2 = (const ulonglong2*)g_Wk;
    #pragma unroll
    for (int i = 0; i < 16; i++) {
        wr0[i] = Wk2[(size_t)(16 + i) * 512 + tid];
        wr1[i] = Wk2[(size_t)(16 + i) * 512 + tid + 256];
    }

    float wi0 = Wih[tid],       bsum0 = bih[tid]       + bhh[tid];
    float wi1 = Wih[tid + 256], bsum1 = bih[tid + 256] + bhh[tid + 256];

    __syncthreads();
    int l0 = sl[0], l1 = sl[1], l2 = sl[2], l3 = sl[3];
    int maxlen = max(max(l0, l1), max(l2, l3));

    #pragma unroll
    for (int m = 0; m < G4; m++)
        for (int t = tid; t < TT; t += 256) sx[m * TT + t] = x[(size_t)sn[m] * TT + t];

    // cell-phase mapping: thread handles cells (mA, uA) and (mB, uA)
    int g0 = tid >> 7;          // gate of row r0 (0=i, 1=f); r1 gate = g0+2
    int u  = tid & 127;
    int mA = g0;                // 0 or 1
    int mB = mA + 2;            // 2 or 3
    int lenA = sl[mA], lenB = sl[mB];
    float* hsA = g_hs + (size_t)sn[mA] * TT * HH + u;
    float* hsB = g_hs + (size_t)sn[mB] * TT * HH + u;
    float cA = 0.0f, cB = 0.0f;
    __syncthreads();

    for (int t = 0; t < maxlen; t++) {
        int cur = t & 1, nxt = cur ^ 1;
        const ulonglong2* hb = (const ulonglong2*)(shf + cur * 512);

        u64 A00 = 0, A01 = 0, A02 = 0, A03 = 0;
        u64 A10 = 0, A11 = 0, A12 = 0, A13 = 0;

        #pragma unroll 4
        for (int p2 = 0; p2 < 16; p2++) {
            ulonglong2 w0 = sWs[p2 * 512 + tid];
            ulonglong2 w1 = sWs[p2 * 512 + tid + 256];
            ulonglong2 h0 = hb[p2], h1 = hb[32 + p2], h2 = hb[64 + p2], h3 = hb[96 + p2];
            A00 = ffma2(w0.x, h0.x, A00); A00 = ffma2(w0.y, h0.y, A00);
            A01 = ffma2(w0.x, h1.x, A01); A01 = ffma2(w0.y, h1.y, A01);
            A02 = ffma2(w0.x, h2.x, A02); A02 = ffma2(w0.y, h2.y, A02);
            A03 = ffma2(w0.x, h3.x, A03); A03 = ffma2(w0.y, h3.y, A03);
            A10 = ffma2(w1.x, h0.x, A10); A10 = ffma2(w1.y, h0.y, A10);
            A11 = ffma2(w1.x, h1.x, A11); A11 = ffma2(w1.y, h1.y, A11);
            A12 = ffma2(w1.x, h2.x, A12); A12 = ffma2(w1.y, h2.y, A12);
            A13 = ffma2(w1.x, h3.x, A13); A13 = ffma2(w1.y, h3.y, A13);
        }
        #pragma unroll
        for (int i = 0; i < 16; i++) {
            int p2 = 16 + i;
            ulonglong2 w0 = wr0[i];
            ulonglong2 w1 = wr1[i];
            ulonglong2 h0 = hb[p2], h1 = hb[32 + p2], h2 = hb[64 + p2], h3 = hb[96 + p2];
            A00 = ffma2(w0.x, h0.x, A00); A00 = ffma2(w0.y, h0.y, A00);
            A01 = ffma2(w0.x, h1.x, A01); A01 = ffma2(w0.y, h1.y, A01);
            A02 = ffma2(w0.x, h2.x, A02); A02 = ffma2(w0.y, h2.y, A02);
            A03 = ffma2(w0.x, h3.x, A03); A03 = ffma2(w0.y, h3.y, A03);
            A10 = ffma2(w1.x, h0.x, A10); A10 = ffma2(w1.y, h0.y, A10);
            A11 = ffma2(w1.x, h1.x, A11); A11 = ffma2(w1.y, h1.y, A11);
            A12 = ffma2(w1.x, h2.x, A12); A12 = ffma2(w1.y, h2.y, A12);
            A13 = ffma2(w1.x, h3.x, A13); A13 = ffma2(w1.y, h3.y, A13);
        }

        float xt0 = sx[t], xt1 = sx[TT + t], xt2 = sx[2 * TT + t], xt3 = sx[3 * TT + t];
        // pre-activations for this thread's two gate-rows, 4 sequences each
        spre[(g0 * 4 + 0) * 128 + u] = f2lo(A00) + f2hi(A00) + xt0 * wi0 + bsum0;
        spre[(g0 * 4 + 1) * 128 + u] = f2lo(A01) + f2hi(A01) + xt1 * wi0 + bsum0;
        spre[(g0 * 4 + 2) * 128 + u] = f2lo(A02) + f2hi(A02) + xt2 * wi0 + bsum0;
        spre[(g0 * 4 + 3) * 128 + u] = f2lo(A03) + f2hi(A03) + xt3 * wi0 + bsum0;
        int g1 = g0 + 2;
        spre[(g1 * 4 + 0) * 128 + u] = f2lo(A10) + f2hi(A10) + xt0 * wi1 + bsum1;
        spre[(g1 * 4 + 1) * 128 + u] = f2lo(A11) + f2hi(A11) + xt1 * wi1 + bsum1;
        spre[(g1 * 4 + 2) * 128 + u] = f2lo(A12) + f2hi(A12) + xt2 * wi1 + bsum1;
        spre[(g1 * 4 + 3) * 128 + u] = f2lo(A13) + f2hi(A13) + xt3 * wi1 + bsum1;
        __syncthreads();

        // cell updates
        {
            float pi = spre[(0 * 4 + mA) * 128 + u];
            float pf = spre[(1 * 4 + mA) * 128 + u];
            float pg = spre[(2 * 4 + mA) * 128 + u];
            float po = spre[(3 * 4 + mA) * 128 + u];
            cA = sigf(pf) * cA + sigf(pi) * tanh_(pg);
            float hv = sigf(po) * tanh_(cA);
            shf[nxt * 512 + mA * 128 + u] = hv;
            if (t < lenA) hsA[(size_t)t * HH] = hv;
        }
        {
            float pi = spre[(0 * 4 + mB) * 128 + u];
            float pf = spre[(1 * 4 + mB) * 128 + u];
            float pg = spre[(2 * 4 + mB) * 128 + u];
            float po = spre[(3 * 4 + mB) * 128 + u];
            cB = sigf(pf) * cB + sigf(pi) * tanh_(pg);
            float hv = sigf(po) * tanh_(cB);
            shf[nxt * 512 + mB * 128 + u] = hv;
            if (t < lenB) hsB[(size_t)t * HH] = hv;
        }
        __syncthreads();
    }

    // zero masked tails so the feats GEMM can ignore lengths
    for (int t = lenA; t < TT; t++) hsA[(size_t)t * HH] = 0.0f;
    for (int t = lenB; t < TT; t++) hsB[(size_t)t * HH] = 0.0f;
}

// ---------------- kernel 6: feats GEMM (split-K, tiled, f32x2) -------------------
// psum[kz][n][j] = sum_{t in chunk} sum_h hs[n][t][h] * W1[j][t*128+h]
__global__ void __launch_bounds__(256) k_feats(const float* __restrict__ W1) {
    __shared__ __align__(16) float sh_hs[TM][HH + 4];     // padded: conflict-free
    __shared__ __align__(16) float sh_w[NINTER][HH];

    int tile = blockIdx.x;        // 0..39
    int kz = blockIdx.y;          // 0..7
    int tid = threadIdx.x;
    int s0 = tid & 15;            // rows s0 and s0+16
    int j0 = (tid >> 4) * 4;      // 4 inter cols
    u64 a0[4] = {0, 0, 0, 0};
    u64 a1[4] = {0, 0, 0, 0};

    int t0 = kz * TCHUNK;
    for (int tt = 0; tt < TCHUNK; tt++) {
        int t = t0 + tt;
        __syncthreads();
        for (int i = tid; i < TM * 32; i += 256) {
            int s = i >> 5, kq = i & 31;
            ((float4*)&sh_hs[s][0])[kq] =
                ((const float4*)(g_hs + ((size_t)(tile * TM + s) * TT + t) * HH))[kq];
        }
        for (int i = tid; i < NINTER * 32; i += 256) {
            int j = i >> 5, kq = i & 31;
            ((float4*)&sh_w[j][0])[kq] =
                ((const float4*)(W1 + (size_t)j * (TT * HH) + (size_t)t * HH))[kq];
        }
        __syncthreads();
        #pragma unroll 4
        for (int kq = 0; kq < 32; kq++) {
            ulonglong2 hA = ((const ulonglong2*)&sh_hs[s0][0])[kq];
            ulonglong2 hB = ((const ulonglong2*)&sh_hs[s0 + 16][0])[kq];
            #pragma unroll
            for (int c = 0; c < 4; c++) {
                ulonglong2 w = ((const ulonglong2*)&sh_w[j0 + c][0])[kq];
                a0[c] = ffma2(hA.x, w.x, a0[c]); a0[c] = ffma2(hA.y, w.y, a0[c]);
                a1[c] = ffma2(hB.x, w.x, a1[c]); a1[c] = ffma2(hB.y, w.y, a1[c]);
            }
        }
    }
    int srow = tile * TM;
    size_t baseA = ((size_t)kz * NN + (srow + s0)) * NINTER + j0;
    size_t baseB = ((size_t)kz * NN + (srow + s0 + 16)) * NINTER + j0;
    #pragma unroll
    for (int c = 0; c < 4; c++) {
        g_psum[baseA + c] = f2lo(a0[c]) + f2hi(a0[c]);
        g_psum[baseB + c] = f2lo(a1[c]) + f2hi(a1[c]);
    }
}

// ---------------- kernel 7: reduce split-K + bias + final linear -----------------
__global__ void __launch_bounds__(256) k_final(
    const float* __restrict__ b1, const float* __restrict__ W2,
    const float* __restrict__ b2, float* __restrict__ out)
{
    __shared__ float sf[SS * NINTER];   // 1280 feats for this batch
    __shared__ float r0[256], r1[256];
    int b = blockIdx.x, tid = threadIdx.x;

    for (int i = tid; i < SS * NINTER; i += 256) {
        int s = i / NINTER, j = i % NINTER;
        size_t nq = (size_t)b * SS + s;
        float v = b1[j];
        #pragma unroll
        for (int kz = 0; kz < KSPLIT; kz++)
            v += g_psum[((size_t)kz * NN + nq) * NINTER + j];
        sf[i] = v;
    }
    __syncthreads();
    float p0 = 0.f, p1 = 0.f;
    for (int i = tid; i < SS * NINTER; i += 256) {
        float f = sf[i];
        p0 += f * W2[i];
        p1 += f * W2[SS * NINTER + i];
    }
    r0[tid] = p0; r1[tid] = p1;
    __syncthreads();
    for (int off = 128; off; off >>= 1) {
        if (tid < off) { r0[tid] += r0[tid + off]; r1[tid] += r1[tid + off]; }
        __syncthreads();
    }
    if (tid == 0) {
        out[b * 2 + 0] = r0[0] + b2[0];
        out[b * 2 + 1] = r1[0] + b2[1];
    }
}

// ---------------- launch ----------------------------------------------------------
extern "C" void kernel_launch(void* const* d_in, const int* in_sizes, int n_in,
                              void* d_out, int out_size)
{
    const float* x   = (const float*)d_in[0];
    // d_in[1] = metadata (unused by the reference computation)
    const float* Wih = (const float*)d_in[2];
    const float* Whh = (const float*)d_in[3];
    const float* bih = (const float*)d_in[4];
    const float* bhh = (const float*)d_in[5];
    const float* W1  = (const float*)d_in[6];
    const float* b1  = (const float*)d_in[7];
    const float* W2  = (const float*)d_in[8];
    const float* b2  = (const float*)d_in[9];
    float* out = (float*)d_out;

    cudaFuncSetAttribute(k_lstm, cudaFuncAttributeMaxDynamicSharedMemorySize, 147456);

    k_zero_hist<<<1, 256>>>();
    k_lens<<<NN, 32>>>(x);
    k_prefix<<<1, 32>>>();
    k_scatter<<<5, 256>>>();
    k_wt<<<64, 256>>>(Whh);
    k_lstm<<<NG, 256, LSTM_SMEM>>>(x, Wih, bih, bhh);
    k_feats<<<dim3(40, KSPLIT), 256>>>(W1);
    k_final<<<BB, 256>>>(b1, W2, b2, out);
}